// round 2
// baseline (speedup 1.0000x reference)
#include <cuda_runtime.h>
#include <math.h>

// ---------------------------------------------------------------------------
// Problem constants (fixed shapes from the reference)
// ---------------------------------------------------------------------------
#define NB    8
#define CIN   512
#define KCC   256
#define KK    19
#define HW    16384            // 128*128
#define TOT   (NB * HW)        // 131072 pixel columns
#define EPSF  1e-5f

// ---------------------------------------------------------------------------
// Scratch (no cudaMalloc allowed) : two 134MB fp32 buffers + tiny k/v
// bufA: t1 (after G1), then context (after attention)
// bufB: q  (after G2)
// ---------------------------------------------------------------------------
__device__ float g_bufA[(size_t)KCC * TOT];
__device__ float g_bufB[(size_t)KCC * TOT];
__device__ float g_kbuf[NB * KCC * KK];
__device__ float g_vbuf[NB * KCC * KK];

// ---------------------------------------------------------------------------
// Proxy path: per batch n,
//   t = bn_relu(w_o1 @ proxy_n)   [256,19]
//   k = bn_relu(w_o2 @ t)         [256,19] -> g_kbuf
//   v = bn_relu(w_d  @ proxy_n)   [256,19] -> g_vbuf
// One block per batch, one thread per output channel.
// ---------------------------------------------------------------------------
__global__ void __launch_bounds__(KCC) proxy_kernel(
    const float* __restrict__ proxy,
    const float* __restrict__ w_o1, const float* __restrict__ o1g,
    const float* __restrict__ o1b,  const float* __restrict__ o1m,
    const float* __restrict__ o1v,
    const float* __restrict__ w_o2, const float* __restrict__ o2g,
    const float* __restrict__ o2b,  const float* __restrict__ o2m,
    const float* __restrict__ o2v,
    const float* __restrict__ w_d,  const float* __restrict__ dgv,
    const float* __restrict__ dbv,  const float* __restrict__ dmv,
    const float* __restrict__ dvv)
{
    const int n  = blockIdx.x;
    const int ch = threadIdx.x;      // 0..255
    const float* p = proxy + n * CIN * KK;

    __shared__ float t_sh[KCC * KK];

    float acc1[KK], accv[KK];
#pragma unroll
    for (int j = 0; j < KK; j++) { acc1[j] = 0.f; accv[j] = 0.f; }

    for (int c = 0; c < CIN; c++) {
        float w1 = __ldg(&w_o1[ch * CIN + c]);
        float wd = __ldg(&w_d [ch * CIN + c]);
#pragma unroll
        for (int j = 0; j < KK; j++) {
            float pv = __ldg(&p[c * KK + j]);
            acc1[j] = fmaf(w1, pv, acc1[j]);
            accv[j] = fmaf(wd, pv, accv[j]);
        }
    }
    {
        float inv = o1g[ch] * rsqrtf(o1v[ch] + EPSF);
        float bt  = o1b[ch] - o1m[ch] * inv;
#pragma unroll
        for (int j = 0; j < KK; j++)
            t_sh[ch * KK + j] = fmaxf(fmaf(acc1[j], inv, bt), 0.f);
    }
    {
        float inv = dgv[ch] * rsqrtf(dvv[ch] + EPSF);
        float bt  = dbv[ch] - dmv[ch] * inv;
#pragma unroll
        for (int j = 0; j < KK; j++)
            g_vbuf[(n * KCC + ch) * KK + j] = fmaxf(fmaf(accv[j], inv, bt), 0.f);
    }
    __syncthreads();

    float acc2[KK];
#pragma unroll
    for (int j = 0; j < KK; j++) acc2[j] = 0.f;
    for (int c = 0; c < KCC; c++) {
        float w2 = __ldg(&w_o2[ch * KCC + c]);
#pragma unroll
        for (int j = 0; j < KK; j++)
            acc2[j] = fmaf(w2, t_sh[c * KK + j], acc2[j]);
    }
    {
        float inv = o2g[ch] * rsqrtf(o2v[ch] + EPSF);
        float bt  = o2b[ch] - o2m[ch] * inv;
#pragma unroll
        for (int j = 0; j < KK; j++)
            g_kbuf[(n * KCC + ch) * KK + j] = fmaxf(fmaf(acc2[j], inv, bt), 0.f);
    }
}

// ---------------------------------------------------------------------------
// Generic GEMM with fused BN+ReLU epilogue.
//   C[row, col] = bn_relu( sum_k A[row,k] * B(k, col) )
// B(k, col):  col = n*HW + hw,  addr = n*bBatch + k*bRow + hw
// C(row,col):                  addr = n*cBatch + row*cRow + hw
// 128x128 block tile, 8x8 per thread, BK=8, 256 threads.
// ---------------------------------------------------------------------------
__global__ void __launch_bounds__(256, 2) gemm_bn_relu(
    const float* __restrict__ A, int K,
    const float* __restrict__ B, int bRow, int bBatch,
    float* __restrict__ C, int cRow, int cBatch,
    const float* __restrict__ gg, const float* __restrict__ bb,
    const float* __restrict__ mm, const float* __restrict__ vv)
{
    __shared__ float As[8][128];
    __shared__ float Bs[8][128];

    const int tid = threadIdx.x;
    const int tx = tid & 15;         // 0..15 -> 8 cols each
    const int ty = tid >> 4;         // 0..15 -> 8 rows each

    const int colBase = blockIdx.x * 128;
    const int rowBase = blockIdx.y * 128;
    const int n      = colBase / HW;         // tile never spans a batch (HW%128==0)
    const int hwBase = colBase - n * HW;

    const float* Bp = B + n * bBatch + hwBase;

    const int am = tid >> 1;                 // 0..127 (row within tile)
    const int ak = (tid & 1) * 4;            // 0 or 4
    const int bk = tid >> 5;                 // 0..7
    const int bc = (tid & 31) * 4;           // 0..124

    float acc[8][8];
#pragma unroll
    for (int i = 0; i < 8; i++)
#pragma unroll
        for (int j = 0; j < 8; j++) acc[i][j] = 0.f;

    for (int k0 = 0; k0 < K; k0 += 8) {
        float4 a4 = *(const float4*)(A + (rowBase + am) * K + k0 + ak);
        float4 b4 = *(const float4*)(Bp + (k0 + bk) * bRow + bc);

        As[ak + 0][am] = a4.x;
        As[ak + 1][am] = a4.y;
        As[ak + 2][am] = a4.z;
        As[ak + 3][am] = a4.w;
        *(float4*)&Bs[bk][bc] = b4;
        __syncthreads();

#pragma unroll
        for (int kk = 0; kk < 8; kk++) {
            float ar[8], br[8];
            ((float4*)ar)[0] = *(const float4*)&As[kk][ty * 8];
            ((float4*)ar)[1] = *(const float4*)&As[kk][ty * 8 + 4];
            ((float4*)br)[0] = *(const float4*)&Bs[kk][tx * 8];
            ((float4*)br)[1] = *(const float4*)&Bs[kk][tx * 8 + 4];
#pragma unroll
            for (int i = 0; i < 8; i++)
#pragma unroll
                for (int j = 0; j < 8; j++)
                    acc[i][j] = fmaf(ar[i], br[j], acc[i][j]);
        }
        __syncthreads();
    }

    // Fused BN + ReLU epilogue, vectorized stores
#pragma unroll
    for (int i = 0; i < 8; i++) {
        const int r = rowBase + ty * 8 + i;
        const float inv = gg[r] * rsqrtf(vv[r] + EPSF);
        const float bt  = bb[r] - mm[r] * inv;
        float* Cp = C + n * cBatch + r * cRow + hwBase + tx * 8;
        float4 o0, o1;
        o0.x = fmaxf(fmaf(acc[i][0], inv, bt), 0.f);
        o0.y = fmaxf(fmaf(acc[i][1], inv, bt), 0.f);
        o0.z = fmaxf(fmaf(acc[i][2], inv, bt), 0.f);
        o0.w = fmaxf(fmaf(acc[i][3], inv, bt), 0.f);
        o1.x = fmaxf(fmaf(acc[i][4], inv, bt), 0.f);
        o1.y = fmaxf(fmaf(acc[i][5], inv, bt), 0.f);
        o1.z = fmaxf(fmaf(acc[i][6], inv, bt), 0.f);
        o1.w = fmaxf(fmaf(acc[i][7], inv, bt), 0.f);
        *(float4*)Cp       = o0;
        *(float4*)(Cp + 4) = o1;
    }
}

// ---------------------------------------------------------------------------
// Fused attention: per pixel column
//   sim[j] = (1/16) * sum_c q[c,col] * k[n,c,j]   (j = 0..18)
//   p = softmax(sim)
//   ctx[c,col] = sum_j p[j] * v[n,c,j]
// ---------------------------------------------------------------------------
__global__ void __launch_bounds__(128) attn_kernel(
    const float* __restrict__ q, float* __restrict__ ctx)
{
    const int colBase = blockIdx.x * 128;
    const int col = colBase + threadIdx.x;
    const int n = colBase / HW;

    __shared__ float k_sh[KCC * KK];
    __shared__ float v_sh[KCC * KK];
    for (int i = threadIdx.x; i < KCC * KK; i += 128) {
        k_sh[i] = g_kbuf[n * KCC * KK + i];
        v_sh[i] = g_vbuf[n * KCC * KK + i];
    }
    __syncthreads();

    float sim[KK];
#pragma unroll
    for (int j = 0; j < KK; j++) sim[j] = 0.f;

    for (int c = 0; c < KCC; c++) {
        float qv = q[c * TOT + col];
#pragma unroll
        for (int j = 0; j < KK; j++)
            sim[j] = fmaf(qv, k_sh[c * KK + j], sim[j]);
    }

    float mx = -1e30f;
#pragma unroll
    for (int j = 0; j < KK; j++) { sim[j] *= 0.0625f; mx = fmaxf(mx, sim[j]); }
    float s = 0.f;
#pragma unroll
    for (int j = 0; j < KK; j++) { sim[j] = __expf(sim[j] - mx); s += sim[j]; }
    const float rs = 1.f / s;
#pragma unroll
    for (int j = 0; j < KK; j++) sim[j] *= rs;

    for (int c = 0; c < KCC; c++) {
        float acc = 0.f;
#pragma unroll
        for (int j = 0; j < KK; j++)
            acc = fmaf(sim[j], v_sh[c * KK + j], acc);
        ctx[c * TOT + col] = acc;
    }
}

// ---------------------------------------------------------------------------
// Launch. Input ordering is detected at runtime:
//   metadata dict order:      x, proxy, w_p1, w_p2, w_o1, w_o2, w_d, w_u,
//                             p1_g..p1_v, p2_*, o1_*, o2_*, d_*, u_*
//   reference-signature order: x, proxy, w_p1, p1_g..p1_v, w_p2, p2_*, ...
// Disambiguator: in_sizes[3] == 256*256 (w_p2) => dict order;
//                in_sizes[3] == 256 (p1_g)     => signature order.
// ---------------------------------------------------------------------------
extern "C" void kernel_launch(void* const* d_in, const int* in_sizes, int n_in,
                              void* d_out, int out_size)
{
    const float* x     = (const float*)d_in[0];
    const float* proxy = (const float*)d_in[1];

    const float *w_p1, *w_p2, *w_o1, *w_o2, *w_d, *w_u;
    const float *p1g,*p1b,*p1m,*p1v, *p2g,*p2b,*p2m,*p2v;
    const float *o1g,*o1b,*o1m,*o1v, *o2g,*o2b,*o2m,*o2v;
    const float *dg,*db,*dm,*dv, *ug,*ub,*um,*uv;

    if (in_sizes[3] == KCC * KCC) {
        // dict order: weights first, then BN params
        w_p1 = (const float*)d_in[2];
        w_p2 = (const float*)d_in[3];
        w_o1 = (const float*)d_in[4];
        w_o2 = (const float*)d_in[5];
        w_d  = (const float*)d_in[6];
        w_u  = (const float*)d_in[7];
        p1g=(const float*)d_in[8];  p1b=(const float*)d_in[9];
        p1m=(const float*)d_in[10]; p1v=(const float*)d_in[11];
        p2g=(const float*)d_in[12]; p2b=(const float*)d_in[13];
        p2m=(const float*)d_in[14]; p2v=(const float*)d_in[15];
        o1g=(const float*)d_in[16]; o1b=(const float*)d_in[17];
        o1m=(const float*)d_in[18]; o1v=(const float*)d_in[19];
        o2g=(const float*)d_in[20]; o2b=(const float*)d_in[21];
        o2m=(const float*)d_in[22]; o2v=(const float*)d_in[23];
        dg =(const float*)d_in[24]; db =(const float*)d_in[25];
        dm =(const float*)d_in[26]; dv =(const float*)d_in[27];
        ug =(const float*)d_in[28]; ub =(const float*)d_in[29];
        um =(const float*)d_in[30]; uv =(const float*)d_in[31];
    } else {
        // reference-signature order
        w_p1 = (const float*)d_in[2];
        p1g=(const float*)d_in[3];  p1b=(const float*)d_in[4];
        p1m=(const float*)d_in[5];  p1v=(const float*)d_in[6];
        w_p2 = (const float*)d_in[7];
        p2g=(const float*)d_in[8];  p2b=(const float*)d_in[9];
        p2m=(const float*)d_in[10]; p2v=(const float*)d_in[11];
        w_o1 = (const float*)d_in[12];
        o1g=(const float*)d_in[13]; o1b=(const float*)d_in[14];
        o1m=(const float*)d_in[15]; o1v=(const float*)d_in[16];
        w_o2 = (const float*)d_in[17];
        o2g=(const float*)d_in[18]; o2b=(const float*)d_in[19];
        o2m=(const float*)d_in[20]; o2v=(const float*)d_in[21];
        w_d  = (const float*)d_in[22];
        dg =(const float*)d_in[23]; db =(const float*)d_in[24];
        dm =(const float*)d_in[25]; dv =(const float*)d_in[26];
        w_u  = (const float*)d_in[27];
        ug =(const float*)d_in[28]; ub =(const float*)d_in[29];
        um =(const float*)d_in[30]; uv =(const float*)d_in[31];
    }

    float* out = (float*)d_out;

    float *bufA = nullptr, *bufB = nullptr;
    cudaGetSymbolAddress((void**)&bufA, g_bufA);
    cudaGetSymbolAddress((void**)&bufB, g_bufB);

    // 1) proxy path -> k, v
    proxy_kernel<<<NB, KCC>>>(proxy,
        w_o1, o1g, o1b, o1m, o1v,
        w_o2, o2g, o2b, o2m, o2v,
        w_d,  dg,  db,  dm,  dv);

    // 2) t1 = bn_relu(w_p1 @ x)        [256, TOT]
    gemm_bn_relu<<<dim3(TOT / 128, KCC / 128), 256>>>(
        w_p1, CIN,
        x, HW, CIN * HW,
        bufA, TOT, HW,
        p1g, p1b, p1m, p1v);

    // 3) q = bn_relu(w_p2 @ t1)        [256, TOT]
    gemm_bn_relu<<<dim3(TOT / 128, KCC / 128), 256>>>(
        w_p2, KCC,
        bufA, TOT, HW,
        bufB, TOT, HW,
        p2g, p2b, p2m, p2v);

    // 4) attention: q -> context (into bufA, reusing t1)
    attn_kernel<<<TOT / 128, 128>>>(bufB, bufA);

    // 5) out = bn_relu(w_u @ context)  [N,512,H,W]
    gemm_bn_relu<<<dim3(TOT / 128, CIN / 128), 256>>>(
        w_u, KCC,
        bufA, TOT, HW,
        out, HW, CIN * HW,
        ug, ub, um, uv);
}

// round 4
// speedup vs baseline: 2.0881x; 2.0881x over previous
#include <cuda_runtime.h>
#include <cuda_bf16.h>
#include <cstdint>
#include <math.h>

#define NB    8
#define CIN   512
#define KCC   256
#define KK    19
#define HW    16384
#define TOT   (NB * HW)
#define EPSF  1e-5f

// ---------------------------------------------------------------------------
// Scratch
// ---------------------------------------------------------------------------
__device__ float g_bufA[(size_t)KCC * TOT];   // t1, then ctx
__device__ float g_bufB[(size_t)KCC * TOT];   // q
__device__ float g_kbuf[NB * KCC * KK];
__device__ float g_vbuf[NB * KCC * KK];

static __device__ __forceinline__ uint32_t smem_u32(const void* p) {
    uint32_t a;
    asm("{ .reg .u64 t; cvta.to.shared.u64 t, %1; cvt.u32.u64 %0, t; }"
        : "=r"(a) : "l"(p));
    return a;
}

// fp32 pair -> packed bf16x2 hi and lo (residual)
static __device__ __forceinline__ void cvt2(float a, float b, uint32_t& h, uint32_t& l) {
    __nv_bfloat16 ha = __float2bfloat16(a), hb = __float2bfloat16(b);
    float la = a - __bfloat162float(ha);
    float lb = b - __bfloat162float(hb);
    __nv_bfloat162 hh = __halves2bfloat162(ha, hb);
    __nv_bfloat162 ll = __halves2bfloat162(__float2bfloat16(la), __float2bfloat16(lb));
    h = *reinterpret_cast<uint32_t*>(&hh);
    l = *reinterpret_cast<uint32_t*>(&ll);
}

#define LDSM4(r0, r1, r2, r3, addr) \
    asm volatile("ldmatrix.sync.aligned.m8n8.x4.shared.b16 {%0,%1,%2,%3}, [%4];" \
                 : "=r"(r0), "=r"(r1), "=r"(r2), "=r"(r3) : "r"(addr))

#define LDSM4T(r0, r1, r2, r3, addr) \
    asm volatile("ldmatrix.sync.aligned.m8n8.x4.trans.shared.b16 {%0,%1,%2,%3}, [%4];" \
                 : "=r"(r0), "=r"(r1), "=r"(r2), "=r"(r3) : "r"(addr))

#define MMA(d, a, b) \
    asm volatile("mma.sync.aligned.m16n8k16.row.col.f32.bf16.bf16.f32 " \
                 "{%0,%1,%2,%3}, {%4,%5,%6,%7}, {%8,%9}, {%0,%1,%2,%3};" \
                 : "+f"((d)[0]), "+f"((d)[1]), "+f"((d)[2]), "+f"((d)[3]) \
                 : "r"((a)[0]), "r"((a)[1]), "r"((a)[2]), "r"((a)[3]), \
                   "r"((b)[0]), "r"((b)[1]))

// ---------------------------------------------------------------------------
// Proxy path (tiny, unchanged from R2): k,v  [n][ch][19]
// ---------------------------------------------------------------------------
__global__ void __launch_bounds__(KCC) proxy_kernel(
    const float* __restrict__ proxy,
    const float* __restrict__ w_o1, const float* __restrict__ o1g,
    const float* __restrict__ o1b,  const float* __restrict__ o1m,
    const float* __restrict__ o1v,
    const float* __restrict__ w_o2, const float* __restrict__ o2g,
    const float* __restrict__ o2b,  const float* __restrict__ o2m,
    const float* __restrict__ o2v,
    const float* __restrict__ w_d,  const float* __restrict__ dgv,
    const float* __restrict__ dbv,  const float* __restrict__ dmv,
    const float* __restrict__ dvv)
{
    const int n  = blockIdx.x;
    const int ch = threadIdx.x;
    const float* p = proxy + n * CIN * KK;

    __shared__ float t_sh[KCC * KK];

    float acc1[KK], accv[KK];
#pragma unroll
    for (int j = 0; j < KK; j++) { acc1[j] = 0.f; accv[j] = 0.f; }

    for (int c = 0; c < CIN; c++) {
        float w1 = __ldg(&w_o1[ch * CIN + c]);
        float wd = __ldg(&w_d [ch * CIN + c]);
#pragma unroll
        for (int j = 0; j < KK; j++) {
            float pv = __ldg(&p[c * KK + j]);
            acc1[j] = fmaf(w1, pv, acc1[j]);
            accv[j] = fmaf(wd, pv, accv[j]);
        }
    }
    {
        float inv = o1g[ch] * rsqrtf(o1v[ch] + EPSF);
        float bt  = o1b[ch] - o1m[ch] * inv;
#pragma unroll
        for (int j = 0; j < KK; j++)
            t_sh[ch * KK + j] = fmaxf(fmaf(acc1[j], inv, bt), 0.f);
    }
    {
        float inv = dgv[ch] * rsqrtf(dvv[ch] + EPSF);
        float bt  = dbv[ch] - dmv[ch] * inv;
#pragma unroll
        for (int j = 0; j < KK; j++)
            g_vbuf[(n * KCC + ch) * KK + j] = fmaxf(fmaf(accv[j], inv, bt), 0.f);
    }
    __syncthreads();

    float acc2[KK];
#pragma unroll
    for (int j = 0; j < KK; j++) acc2[j] = 0.f;
    for (int c = 0; c < KCC; c++) {
        float w2 = __ldg(&w_o2[ch * KCC + c]);
#pragma unroll
        for (int j = 0; j < KK; j++)
            acc2[j] = fmaf(w2, t_sh[c * KK + j], acc2[j]);
    }
    {
        float inv = o2g[ch] * rsqrtf(o2v[ch] + EPSF);
        float bt  = o2b[ch] - o2m[ch] * inv;
#pragma unroll
        for (int j = 0; j < KK; j++)
            g_kbuf[(n * KCC + ch) * KK + j] = fmaxf(fmaf(acc2[j], inv, bt), 0.f);
    }
}

// ---------------------------------------------------------------------------
// HMMA GEMM: D[m, pix] = bn_relu( sum_k A[m,k] * B(k, pix) ),
// 3-term bf16 hi/lo split on tensor cores.
// BM=256 BN=128 BK=32, 256 threads, warp tile 64x64 (warp grid 4m x 2n).
// B(k,pix): addr = nbat*bBatch + k*bRow + hw     (pix = nbat*HW + hw)
// C(m,pix): addr = nbat*cBatch + m*cRow + hw
// ---------------------------------------------------------------------------
#define OFF_AH 0
#define OFF_AL 16384
#define OFF_BH 32768
#define OFF_BL 40960

__global__ void __launch_bounds__(256, 1) gemm_mma(
    const float* __restrict__ A, int KT,
    const float* __restrict__ B, int bRow, long bBatch,
    float* __restrict__ C, int cRow, long cBatch,
    const float* __restrict__ gg, const float* __restrict__ bb,
    const float* __restrict__ mm, const float* __restrict__ vv)
{
    __shared__ __align__(128) unsigned char sm[49152];
    const uint32_t sb = smem_u32(sm);

    const int tid  = threadIdx.x;
    const int lane = tid & 31;
    const int w    = tid >> 5;
    const int mw   = (w >> 1) * 64;     // warp m offset in 256
    const int nw   = (w & 1) * 64;      // warp n offset in 128

    const int nBase = blockIdx.x * 128;
    const int mBase = blockIdx.y * 256;
    const int nbat  = nBase >> 14;
    const int hw0   = nBase & (HW - 1);
    const float* Bp = B + (size_t)nbat * bBatch + hw0;

    // staging indices
    const int arow0 = tid >> 3;         // +32*i rows
    const int akq   = tid & 7;          // float4 col within 32-k row
    const int brow0 = tid >> 5;         // +8*i k-rows
    const int bl32  = tid & 31;         // float4 col within 128-n row

    float acc[4][8][4];
#pragma unroll
    for (int i = 0; i < 4; i++)
#pragma unroll
        for (int g = 0; g < 8; g++)
#pragma unroll
            for (int r = 0; r < 4; r++) acc[i][g][r] = 0.f;

    float4 pa[8], pb[4];
    // prefetch k0 = 0
#pragma unroll
    for (int i = 0; i < 8; i++)
        pa[i] = __ldg((const float4*)(A + (size_t)(mBase + arow0 + 32 * i) * KT) + akq);
#pragma unroll
    for (int i = 0; i < 4; i++)
        pb[i] = __ldg((const float4*)(Bp + (size_t)(brow0 + 8 * i) * bRow) + bl32);

    for (int k0 = 0; k0 < KT; k0 += 32) {
        __syncthreads();    // previous compute done before overwriting smem
        // ---- stage registers -> smem (convert to hi/lo bf16, swizzled) ----
#pragma unroll
        for (int i = 0; i < 8; i++) {
            const int m = arow0 + 32 * i;
            uint32_t h0, h1, l0, l1;
            cvt2(pa[i].x, pa[i].y, h0, l0);
            cvt2(pa[i].z, pa[i].w, h1, l1);
            const uint32_t off = (uint32_t)(m * 64 + (((akq >> 1) ^ ((m >> 1) & 3)) << 4)
                                            + ((akq & 1) << 3));
            *(uint2*)(sm + OFF_AH + off) = make_uint2(h0, h1);
            *(uint2*)(sm + OFF_AL + off) = make_uint2(l0, l1);
        }
#pragma unroll
        for (int i = 0; i < 4; i++) {
            const int k = brow0 + 8 * i;
            uint32_t h0, h1, l0, l1;
            cvt2(pb[i].x, pb[i].y, h0, l0);
            cvt2(pb[i].z, pb[i].w, h1, l1);
            const uint32_t off = (uint32_t)(k * 256 + (((bl32 >> 1) ^ (k & 7)) << 4)
                                            + ((bl32 & 1) << 3));
            *(uint2*)(sm + OFF_BH + off) = make_uint2(h0, h1);
            *(uint2*)(sm + OFF_BL + off) = make_uint2(l0, l1);
        }
        __syncthreads();

        // ---- prefetch next tile while computing ----
        if (k0 + 32 < KT) {
#pragma unroll
            for (int i = 0; i < 8; i++)
                pa[i] = __ldg((const float4*)(A + (size_t)(mBase + arow0 + 32 * i) * KT
                                              + (k0 + 32)) + akq);
#pragma unroll
            for (int i = 0; i < 4; i++)
                pb[i] = __ldg((const float4*)(Bp + (size_t)(k0 + 32 + brow0 + 8 * i) * bRow)
                              + bl32);
        }

        // ---- compute: 2 x k16, 3 precision terms ----
#pragma unroll
        for (int kk = 0; kk < 32; kk += 16) {
            uint32_t bf[8][2], af[4][4];
            const int krow = kk + (lane & 15);
            const int ncolHalf = (lane >> 4) * 8;
            const int arow = (lane & 15);
            const int acol = kk + (lane >> 4) * 8;

            // B hi frags
#pragma unroll
            for (int ni = 0; ni < 4; ni++) {
                const int nn = nw + ni * 16 + ncolHalf;
                uint32_t ad = sb + OFF_BH
                    + (uint32_t)(krow * 256 + ((((nn >> 3) ^ (krow & 7))) << 4));
                LDSM4T(bf[2 * ni][0], bf[2 * ni][1], bf[2 * ni + 1][0], bf[2 * ni + 1][1], ad);
            }
            // A hi frags
#pragma unroll
            for (int mi = 0; mi < 4; mi++) {
                const int r = mw + mi * 16 + arow;
                uint32_t ad = sb + OFF_AH
                    + (uint32_t)(r * 64 + ((((acol >> 3) ^ ((r >> 1) & 3))) << 4));
                LDSM4(af[mi][0], af[mi][1], af[mi][2], af[mi][3], ad);
            }
            // hi * hi
#pragma unroll
            for (int mi = 0; mi < 4; mi++)
#pragma unroll
                for (int g = 0; g < 8; g++) MMA(acc[mi][g], af[mi], bf[g]);
            // A lo frags (overwrite)
#pragma unroll
            for (int mi = 0; mi < 4; mi++) {
                const int r = mw + mi * 16 + arow;
                uint32_t ad = sb + OFF_AL
                    + (uint32_t)(r * 64 + ((((acol >> 3) ^ ((r >> 1) & 3))) << 4));
                LDSM4(af[mi][0], af[mi][1], af[mi][2], af[mi][3], ad);
            }
            // lo * hi
#pragma unroll
            for (int mi = 0; mi < 4; mi++)
#pragma unroll
                for (int g = 0; g < 8; g++) MMA(acc[mi][g], af[mi], bf[g]);
            // B lo frags (overwrite bf)
#pragma unroll
            for (int ni = 0; ni < 4; ni++) {
                const int nn = nw + ni * 16 + ncolHalf;
                uint32_t ad = sb + OFF_BL
                    + (uint32_t)(krow * 256 + ((((nn >> 3) ^ (krow & 7))) << 4));
                LDSM4T(bf[2 * ni][0], bf[2 * ni][1], bf[2 * ni + 1][0], bf[2 * ni + 1][1], ad);
            }
            // A hi again
#pragma unroll
            for (int mi = 0; mi < 4; mi++) {
                const int r = mw + mi * 16 + arow;
                uint32_t ad = sb + OFF_AH
                    + (uint32_t)(r * 64 + ((((acol >> 3) ^ ((r >> 1) & 3))) << 4));
                LDSM4(af[mi][0], af[mi][1], af[mi][2], af[mi][3], ad);
            }
            // hi * lo
#pragma unroll
            for (int mi = 0; mi < 4; mi++)
#pragma unroll
                for (int g = 0; g < 8; g++) MMA(acc[mi][g], af[mi], bf[g]);
        }
    }

    // ---- epilogue: BN + ReLU, float2 stores ----
#pragma unroll
    for (int mi = 0; mi < 4; mi++) {
        const int m_t = mBase + mw + mi * 16 + (lane >> 2);
        const int m_b = m_t + 8;
        const float inv_t = gg[m_t] * rsqrtf(vv[m_t] + EPSF);
        const float bt_t  = bb[m_t] - mm[m_t] * inv_t;
        const float inv_b = gg[m_b] * rsqrtf(vv[m_b] + EPSF);
        const float bt_b  = bb[m_b] - mm[m_b] * inv_b;
        float* rowT = C + (size_t)nbat * cBatch + (size_t)m_t * cRow;
        float* rowB = C + (size_t)nbat * cBatch + (size_t)m_b * cRow;
#pragma unroll
        for (int g = 0; g < 8; g++) {
            const int hw = hw0 + nw + g * 8 + 2 * (lane & 3);
            float2 vt, vb2;
            vt.x  = fmaxf(fmaf(acc[mi][g][0], inv_t, bt_t), 0.f);
            vt.y  = fmaxf(fmaf(acc[mi][g][1], inv_t, bt_t), 0.f);
            vb2.x = fmaxf(fmaf(acc[mi][g][2], inv_b, bt_b), 0.f);
            vb2.y = fmaxf(fmaf(acc[mi][g][3], inv_b, bt_b), 0.f);
            *(float2*)(rowT + hw) = vt;
            *(float2*)(rowB + hw) = vb2;
        }
    }
}

// ---------------------------------------------------------------------------
// Attention: 128 threads, 4 pixels/thread (amortize k/v LDS broadcasts).
// q, ctx channel-major [256][TOT].
// ---------------------------------------------------------------------------
__global__ void __launch_bounds__(128) attn_kernel(
    const float* __restrict__ q, float* __restrict__ ctx)
{
    __shared__ float k_sh[KCC * KK];
    __shared__ float v_sh[KCC * KK];
    const int pixBase = blockIdx.x * 512;
    const int n = pixBase >> 14;
    for (int i = threadIdx.x; i < KCC * KK; i += 128) {
        k_sh[i] = g_kbuf[n * KCC * KK + i];
        v_sh[i] = g_vbuf[n * KCC * KK + i];
    }
    __syncthreads();

    const int c0 = pixBase + threadIdx.x;
    float sim[4][KK];
#pragma unroll
    for (int u = 0; u < 4; u++)
#pragma unroll
        for (int j = 0; j < KK; j++) sim[u][j] = 0.f;

    for (int c = 0; c < KCC; c++) {
        const float* qc = q + (size_t)c * TOT + c0;
        float q0 = qc[0], q1 = qc[128], q2 = qc[256], q3 = qc[384];
#pragma unroll
        for (int j = 0; j < KK; j++) {
            const float kc = k_sh[c * KK + j];
            sim[0][j] = fmaf(q0, kc, sim[0][j]);
            sim[1][j] = fmaf(q1, kc, sim[1][j]);
            sim[2][j] = fmaf(q2, kc, sim[2][j]);
            sim[3][j] = fmaf(q3, kc, sim[3][j]);
        }
    }

#pragma unroll
    for (int u = 0; u < 4; u++) {
        float mx = -1e30f;
#pragma unroll
        for (int j = 0; j < KK; j++) { sim[u][j] *= 0.0625f; mx = fmaxf(mx, sim[u][j]); }
        float s = 0.f;
#pragma unroll
        for (int j = 0; j < KK; j++) { sim[u][j] = __expf(sim[u][j] - mx); s += sim[u][j]; }
        const float rs = 1.f / s;
#pragma unroll
        for (int j = 0; j < KK; j++) sim[u][j] *= rs;
    }

    for (int c = 0; c < KCC; c++) {
        float a0 = 0.f, a1 = 0.f, a2 = 0.f, a3 = 0.f;
#pragma unroll
        for (int j = 0; j < KK; j++) {
            const float vc = v_sh[c * KK + j];
            a0 = fmaf(sim[0][j], vc, a0);
            a1 = fmaf(sim[1][j], vc, a1);
            a2 = fmaf(sim[2][j], vc, a2);
            a3 = fmaf(sim[3][j], vc, a3);
        }
        float* oc = ctx + (size_t)c * TOT + c0;
        oc[0] = a0; oc[128] = a1; oc[256] = a2; oc[384] = a3;
    }
}

// ---------------------------------------------------------------------------
// Launch (runtime input-order disambiguation, as R2)
// ---------------------------------------------------------------------------
extern "C" void kernel_launch(void* const* d_in, const int* in_sizes, int n_in,
                              void* d_out, int out_size)
{
    const float* x     = (const float*)d_in[0];
    const float* proxy = (const float*)d_in[1];

    const float *w_p1, *w_p2, *w_o1, *w_o2, *w_d, *w_u;
    const float *p1g,*p1b,*p1m,*p1v, *p2g,*p2b,*p2m,*p2v;
    const float *o1g,*o1b,*o1m,*o1v, *o2g,*o2b,*o2m,*o2v;
    const float *dg,*db,*dm,*dv, *ug,*ub,*um,*uv;

    if (in_sizes[3] == KCC * KCC) {
        w_p1=(const float*)d_in[2]; w_p2=(const float*)d_in[3];
        w_o1=(const float*)d_in[4]; w_o2=(const float*)d_in[5];
        w_d =(const float*)d_in[6]; w_u =(const float*)d_in[7];
        p1g=(const float*)d_in[8];  p1b=(const float*)d_in[9];
        p1m=(const float*)d_in[10]; p1v=(const float*)d_in[11];
        p2g=(const float*)d_in[12]; p2b=(const float*)d_in[13];
        p2m=(const float*)d_in[14]; p2v=(const float*)d_in[15];
        o1g=(const float*)d_in[16]; o1b=(const float*)d_in[17];
        o1m=(const float*)d_in[18]; o1v=(const float*)d_in[19];
        o2g=(const float*)d_in[20]; o2b=(const float*)d_in[21];
        o2m=(const float*)d_in[22]; o2v=(const float*)d_in[23];
        dg =(const float*)d_in[24]; db =(const float*)d_in[25];
        dm =(const float*)d_in[26]; dv =(const float*)d_in[27];
        ug =(const float*)d_in[28]; ub =(const float*)d_in[29];
        um =(const float*)d_in[30]; uv =(const float*)d_in[31];
    } else {
        w_p1=(const float*)d_in[2];
        p1g=(const float*)d_in[3];  p1b=(const float*)d_in[4];
        p1m=(const float*)d_in[5];  p1v=(const float*)d_in[6];
        w_p2=(const float*)d_in[7];
        p2g=(const float*)d_in[8];  p2b=(const float*)d_in[9];
        p2m=(const float*)d_in[10]; p2v=(const float*)d_in[11];
        w_o1=(const float*)d_in[12];
        o1g=(const float*)d_in[13]; o1b=(const float*)d_in[14];
        o1m=(const float*)d_in[15]; o1v=(const float*)d_in[16];
        w_o2=(const float*)d_in[17];
        o2g=(const float*)d_in[18]; o2b=(const float*)d_in[19];
        o2m=(const float*)d_in[20]; o2v=(const float*)d_in[21];
        w_d =(const float*)d_in[22];
        dg =(const float*)d_in[23]; db =(const float*)d_in[24];
        dm =(const float*)d_in[25]; dv =(const float*)d_in[26];
        w_u =(const float*)d_in[27];
        ug =(const float*)d_in[28]; ub =(const float*)d_in[29];
        um =(const float*)d_in[30]; uv =(const float*)d_in[31];
    }

    float* out = (float*)d_out;

    float *bufA = nullptr, *bufB = nullptr;
    cudaGetSymbolAddress((void**)&bufA, g_bufA);
    cudaGetSymbolAddress((void**)&bufB, g_bufB);

    // 1) proxy -> k, v
    proxy_kernel<<<NB, KCC>>>(proxy,
        w_o1, o1g, o1b, o1m, o1v,
        w_o2, o2g, o2b, o2m, o2v,
        w_d,  dg,  db,  dm,  dv);

    // 2) t1 = bn_relu(w_p1 @ x)   [256][TOT], one M-pass (BM=256)
    gemm_mma<<<dim3(TOT / 128, 1), 256>>>(
        w_p1, CIN,
        x, HW, (long)CIN * HW,
        bufA, TOT, HW,
        p1g, p1b, p1m, p1v);

    // 3) q = bn_relu(w_p2 @ t1)   [256][TOT]
    gemm_mma<<<dim3(TOT / 128, 1), 256>>>(
        w_p2, KCC,
        bufA, TOT, HW,
        bufB, TOT, HW,
        p2g, p2b, p2m, p2v);

    // 4) attention q -> ctx (reuses bufA)
    attn_kernel<<<TOT / 512, 128>>>(bufB, bufA);

    // 5) out = bn_relu(w_u @ ctx) -> NCHW, two M-passes
    gemm_mma<<<dim3(TOT / 128, CIN / 256), 256>>>(
        w_u, KCC,
        bufA, TOT, HW,
        out, HW, (long)CIN * HW,
        ug, ub, um, uv);
}